// round 2
// baseline (speedup 1.0000x reference)
#include <cuda_runtime.h>

// MultiHeadAttention: B=2, N=2048, C=1024, H=16, D=64, fp32.
// Pipeline: qkv_kernel (GEMM + scatter to [B,H,D,N]/[B,H,N,D]) ->
//           attn_kernel (flash attention, online softmax in registers) ->
//           proj_kernel (GEMM + bias -> d_out).

#define BB 2
#define NN 2048
#define CC 1024
#define HH 16
#define DD 64
#define MM (BB * NN)          // 4096
#define SCALE_F 0.125f        // 64^-0.5

// Scratch (device globals: allocation-free rule)
__device__ float g_q[(size_t)BB * HH * DD * NN];   // [B,H,D,N]
__device__ float g_k[(size_t)BB * HH * DD * NN];   // [B,H,D,N]
__device__ float g_v[(size_t)BB * HH * NN * DD];   // [B,H,N,D]
__device__ float g_att[(size_t)MM * CC];           // [B,N,C] attention output

// ---------------------------------------------------------------------------
// QKV GEMM: out[r][c] = sum_k x[r][k] * w_qkv[c][k], scattered to Q/K/V.
// 64x64 tile, 16 k-chunk, 256 threads, 4x4 per thread.
// ---------------------------------------------------------------------------
__global__ __launch_bounds__(256) void qkv_kernel(const float* __restrict__ x,
                                                  const float* __restrict__ w) {
    __shared__ float As[16 * 68];   // [k][row], pad 68 for conflict-free float4
    __shared__ float Bs[16 * 68];   // [k][col]
    const int t = threadIdx.x;
    const int tx = t & 15, ty = t >> 4;
    const int row0 = blockIdx.y * 64;
    const int col0 = blockIdx.x * 64;
    float acc[4][4] = {};
    const float4* As4 = (const float4*)As;
    const float4* Bs4 = (const float4*)Bs;

    for (int k0 = 0; k0 < CC; k0 += 16) {
        __syncthreads();
#pragma unroll
        for (int i = 0; i < 4; i++) {
            int idx = t + i * 256;
            int r = idx >> 4, c = idx & 15;
            As[c * 68 + r] = __ldg(&x[(size_t)(row0 + r) * CC + k0 + c]);
            Bs[c * 68 + r] = __ldg(&w[(size_t)(col0 + r) * CC + k0 + c]);
        }
        __syncthreads();
#pragma unroll
        for (int kk = 0; kk < 16; kk++) {
            float4 a = As4[kk * 17 + ty];
            float4 b = Bs4[kk * 17 + tx];
            float av[4] = {a.x, a.y, a.z, a.w};
            float bv[4] = {b.x, b.y, b.z, b.w};
#pragma unroll
            for (int i = 0; i < 4; i++)
#pragma unroll
                for (int j = 0; j < 4; j++) acc[i][j] += av[i] * bv[j];
        }
    }

#pragma unroll
    for (int i = 0; i < 4; i++) {
        int r = row0 + ty * 4 + i;
        int b = r >> 11;               // / NN
        int n = r & (NN - 1);
#pragma unroll
        for (int j = 0; j < 4; j++) {
            int c = col0 + tx * 4 + j;
            int which = c >> 10;       // 0=Q 1=K 2=V
            int rem = c & (CC - 1);
            int h = rem >> 6;
            int d = rem & (DD - 1);
            float v = acc[i][j];
            if (which == 0)
                g_q[((size_t)((b * HH + h) * DD + d)) * NN + n] = v;
            else if (which == 1)
                g_k[((size_t)((b * HH + h) * DD + d)) * NN + n] = v;
            else
                g_v[((size_t)((b * HH + h) * NN + n)) * DD + d] = v;
        }
    }
}

// ---------------------------------------------------------------------------
// Flash attention. Block = 64 queries of one (b,h). 256 threads (16x16),
// 4x4 per thread. Q/K tiles are d-major in smem ([d][row]) -> conflict-free
// float4 reads. Softmax runs in registers with 16-lane shfl reductions
// (each S row is owned by one half-warp). Static smem = exactly 48 KB.
// ---------------------------------------------------------------------------
__global__ __launch_bounds__(256) void attn_kernel() {
    __shared__ float Qs[DD * 64];   // [d][qrow]
    __shared__ float Ks[DD * 64];   // [d][kcol]
    __shared__ float Vs[64 * DD];   // [krow][d]
    const int t = threadIdx.x;
    const int tx = t & 15, ty = t >> 4;
    const int bh = blockIdx.z * HH + blockIdx.y;
    const int q0 = blockIdx.x * 64;
    const float* __restrict__ Qg = g_q + (size_t)bh * DD * NN;
    const float* __restrict__ Kg = g_k + (size_t)bh * DD * NN;
    const float* __restrict__ Vg = g_v + (size_t)bh * NN * DD;

    // Load Q tile: Qs[d][r] = Qg[d*NN + q0 + r]
#pragma unroll
    for (int i = 0; i < 16; i++) {
        int idx = t + i * 256;
        int d = idx >> 6, r = idx & 63;
        Qs[idx] = __ldg(&Qg[(size_t)d * NN + q0 + r]);
    }

    float O[4][4] = {};
    float m_run[4], l_run[4];
#pragma unroll
    for (int i = 0; i < 4; i++) { m_run[i] = -1e30f; l_run[i] = 0.f; }

    const float4* Qs4 = (const float4*)Qs;
    const float4* Ks4 = (const float4*)Ks;
    const float4* Vs4 = (const float4*)Vs;

    for (int k0 = 0; k0 < NN; k0 += 64) {
        __syncthreads();   // previous iteration's smem reads done (also Qs visible)
#pragma unroll
        for (int i = 0; i < 16; i++) {
            int idx = t + i * 256;
            int d = idx >> 6, c = idx & 63;
            Ks[idx] = __ldg(&Kg[(size_t)d * NN + k0 + c]);
            Vs[idx] = __ldg(&Vg[(size_t)k0 * DD + idx]);   // [krow][d], coalesced
        }
        __syncthreads();

        // S = Q K^T (64x64), 4x4 per thread
        float s[4][4] = {};
#pragma unroll 16
        for (int d = 0; d < DD; d++) {
            float4 a = Qs4[d * 16 + ty];
            float4 b = Ks4[d * 16 + tx];
            float av[4] = {a.x, a.y, a.z, a.w};
            float bv[4] = {b.x, b.y, b.z, b.w};
#pragma unroll
            for (int i = 0; i < 4; i++)
#pragma unroll
                for (int j = 0; j < 4; j++) s[i][j] += av[i] * bv[j];
        }

        // Online softmax, per row, across the owning half-warp (16 lanes)
        float p[4][4];
#pragma unroll
        for (int i = 0; i < 4; i++) {
#pragma unroll
            for (int j = 0; j < 4; j++) s[i][j] *= SCALE_F;
            float mx = fmaxf(fmaxf(s[i][0], s[i][1]), fmaxf(s[i][2], s[i][3]));
#pragma unroll
            for (int off = 1; off < 16; off <<= 1)
                mx = fmaxf(mx, __shfl_xor_sync(0xffffffffu, mx, off, 16));
            float mnew = fmaxf(m_run[i], mx);
            float corr = __expf(m_run[i] - mnew);
            float rs = 0.f;
#pragma unroll
            for (int j = 0; j < 4; j++) {
                float e = __expf(s[i][j] - mnew);
                p[i][j] = e;
                rs += e;
            }
#pragma unroll
            for (int off = 1; off < 16; off <<= 1)
                rs += __shfl_xor_sync(0xffffffffu, rs, off, 16);
            l_run[i] = l_run[i] * corr + rs;
            m_run[i] = mnew;
#pragma unroll
            for (int j = 0; j < 4; j++) O[i][j] *= corr;
        }

        // O += P @ V. P[i][kk] is broadcast from its owning lane via shfl.
#pragma unroll 16
        for (int kk = 0; kk < 64; kk++) {
            float4 v = Vs4[kk * 16 + tx];
            int src = kk >> 2;
            float pv[4];
#pragma unroll
            for (int i = 0; i < 4; i++)
                pv[i] = __shfl_sync(0xffffffffu, p[i][kk & 3], src, 16);
            float vv[4] = {v.x, v.y, v.z, v.w};
#pragma unroll
            for (int i = 0; i < 4; i++)
#pragma unroll
                for (int j = 0; j < 4; j++) O[i][j] += pv[i] * vv[j];
        }
    }

    // Write O / l to g_att[b, n, h*64 + d]
    const int b = blockIdx.z;
    const int h = blockIdx.y;
#pragma unroll
    for (int i = 0; i < 4; i++) {
        int n = q0 + ty * 4 + i;
        float inv = 1.0f / l_run[i];
        float4 o4 = make_float4(O[i][0] * inv, O[i][1] * inv, O[i][2] * inv, O[i][3] * inv);
        *(float4*)(g_att + ((size_t)(b * NN + n)) * CC + h * DD + tx * 4) = o4;
    }
}

// ---------------------------------------------------------------------------
// Proj GEMM: out[r][c] = sum_k att[r][k] * w_proj[c][k] + b_proj[c]
// ---------------------------------------------------------------------------
__global__ __launch_bounds__(256) void proj_kernel(const float* __restrict__ w,
                                                   const float* __restrict__ bias,
                                                   float* __restrict__ out) {
    __shared__ float As[16 * 68];
    __shared__ float Bs[16 * 68];
    const int t = threadIdx.x;
    const int tx = t & 15, ty = t >> 4;
    const int row0 = blockIdx.y * 64;
    const int col0 = blockIdx.x * 64;
    float acc[4][4] = {};
    const float4* As4 = (const float4*)As;
    const float4* Bs4 = (const float4*)Bs;

    for (int k0 = 0; k0 < CC; k0 += 16) {
        __syncthreads();
#pragma unroll
        for (int i = 0; i < 4; i++) {
            int idx = t + i * 256;
            int r = idx >> 4, c = idx & 15;
            As[c * 68 + r] = g_att[(size_t)(row0 + r) * CC + k0 + c];
            Bs[c * 68 + r] = __ldg(&w[(size_t)(col0 + r) * CC + k0 + c]);
        }
        __syncthreads();
#pragma unroll
        for (int kk = 0; kk < 16; kk++) {
            float4 a = As4[kk * 17 + ty];
            float4 b = Bs4[kk * 17 + tx];
            float av[4] = {a.x, a.y, a.z, a.w};
            float bv[4] = {b.x, b.y, b.z, b.w};
#pragma unroll
            for (int i = 0; i < 4; i++)
#pragma unroll
                for (int j = 0; j < 4; j++) acc[i][j] += av[i] * bv[j];
        }
    }

#pragma unroll
    for (int i = 0; i < 4; i++) {
        int r = row0 + ty * 4 + i;
        int c = col0 + tx * 4;
        float4 o4 = make_float4(acc[i][0] + bias[c + 0], acc[i][1] + bias[c + 1],
                                acc[i][2] + bias[c + 2], acc[i][3] + bias[c + 3]);
        *(float4*)(out + (size_t)r * CC + c) = o4;
    }
}

// ---------------------------------------------------------------------------
extern "C" void kernel_launch(void* const* d_in, const int* in_sizes, int n_in,
                              void* d_out, int out_size) {
    const float* x      = (const float*)d_in[0];
    const float* w_qkv  = (const float*)d_in[1];
    const float* w_proj = (const float*)d_in[2];
    const float* b_proj = (const float*)d_in[3];
    float* out = (float*)d_out;

    dim3 g1(3 * CC / 64, MM / 64);          // 48 x 64
    qkv_kernel<<<g1, 256>>>(x, w_qkv);

    dim3 g2(NN / 64, HH, BB);               // 32 x 16 x 2
    attn_kernel<<<g2, 256>>>();

    dim3 g3(CC / 64, MM / 64);              // 16 x 64
    proj_kernel<<<g3, 256>>>(w_proj, b_proj, out);
}

// round 3
// speedup vs baseline: 1.0654x; 1.0654x over previous
#include <cuda_runtime.h>

// MultiHeadAttention: B=2, N=2048, C=1024, H=16, D=64, fp32.
// R3: 8x8 register blocking everywhere (fix L1-bound 4x4 version).
//   qkv_kernel : 128x128x8 SGEMM + scatter to Q[B,H,D,N] K[B,H,D,N] V[B,H,N,D]
//   attn_kernel: flash attention, 128q x 128k tiles, 96KB dynamic smem,
//                softmax in registers (16-lane shfl), PV via shfl broadcast
//   proj_kernel: 128x128x8 SGEMM + bias -> d_out

#define BB 2
#define NN 2048
#define CC 1024
#define HH 16
#define DD 64
#define MM (BB * NN)          // 4096
#define SCALE_F 0.125f        // 64^-0.5

__device__ float g_q[(size_t)BB * HH * DD * NN];   // [B,H,D,N]
__device__ float g_k[(size_t)BB * HH * DD * NN];   // [B,H,D,N]
__device__ float g_v[(size_t)BB * HH * NN * DD];   // [B,H,N,D]
__device__ float g_att[(size_t)MM * CC];           // [B,N,C]

// ---------------------------------------------------------------------------
// 128x128 tile, BK=8, 256 threads (16x16), 8x8 per thread.
// As/Bs stored [k][m] with pad 132 (conflict-free loads + stores).
// ---------------------------------------------------------------------------
__global__ __launch_bounds__(256) void qkv_kernel(const float* __restrict__ x,
                                                  const float* __restrict__ w) {
    __shared__ float As[8][132];
    __shared__ float Bs[8][132];
    const int t = threadIdx.x;
    const int tx = t & 15, ty = t >> 4;
    const int row0 = blockIdx.y * 128;
    const int col0 = blockIdx.x * 128;
    const int lr = t >> 1;            // 0..127 row within tile for loading
    const int lc = (t & 1) * 4;       // 0 or 4: k offset
    float acc[8][8] = {};
    const float4* As4 = (const float4*)&As[0][0];
    const float4* Bs4 = (const float4*)&Bs[0][0];

    for (int k0 = 0; k0 < CC; k0 += 8) {
        __syncthreads();
        float4 av = *(const float4*)&x[(size_t)(row0 + lr) * CC + k0 + lc];
        float4 bv = *(const float4*)&w[(size_t)(col0 + lr) * CC + k0 + lc];
        As[lc + 0][lr] = av.x; As[lc + 1][lr] = av.y;
        As[lc + 2][lr] = av.z; As[lc + 3][lr] = av.w;
        Bs[lc + 0][lr] = bv.x; Bs[lc + 1][lr] = bv.y;
        Bs[lc + 2][lr] = bv.z; Bs[lc + 3][lr] = bv.w;
        __syncthreads();
#pragma unroll
        for (int kk = 0; kk < 8; kk++) {
            float4 a0 = As4[kk * 33 + ty * 2];
            float4 a1 = As4[kk * 33 + ty * 2 + 1];
            float4 b0 = Bs4[kk * 33 + tx * 2];
            float4 b1 = Bs4[kk * 33 + tx * 2 + 1];
            float aa[8] = {a0.x, a0.y, a0.z, a0.w, a1.x, a1.y, a1.z, a1.w};
            float bb[8] = {b0.x, b0.y, b0.z, b0.w, b1.x, b1.y, b1.z, b1.w};
#pragma unroll
            for (int i = 0; i < 8; i++)
#pragma unroll
                for (int j = 0; j < 8; j++) acc[i][j] += aa[i] * bb[j];
        }
    }

    // Scatter. Whole block lies in one of Q/K/V (col tile 128 divides 1024).
    const int which = col0 >> 10;           // 0=Q 1=K 2=V
    const int rem0 = (col0 & 1023) + tx * 8;
    const int h = rem0 >> 6;                // 8-wide chunk never crosses head
    const int d0 = rem0 & 63;
#pragma unroll
    for (int i = 0; i < 8; i++) {
        int r = row0 + ty * 8 + i;
        int b = r >> 11;
        int n = r & (NN - 1);
        if (which == 2) {
            float* p = g_v + (((size_t)(b * HH + h) * NN + n) * DD + d0);
            *(float4*)(p)     = make_float4(acc[i][0], acc[i][1], acc[i][2], acc[i][3]);
            *(float4*)(p + 4) = make_float4(acc[i][4], acc[i][5], acc[i][6], acc[i][7]);
        } else {
            float* g = (which == 0) ? g_q : g_k;
#pragma unroll
            for (int j = 0; j < 8; j++)
                g[((size_t)((b * HH + h) * DD + d0 + j)) * NN + n] = acc[i][j];
        }
    }
}

// ---------------------------------------------------------------------------
// Flash attention v2: block = 128 queries of one (b,h), k-tiles of 128.
// 256 threads (16x16), 8x8 S-fragment per thread, O is 8x4.
// Dynamic smem 96KB: Qs[64][128], Ks[64][128], Vs[128][64].
// ---------------------------------------------------------------------------
__global__ __launch_bounds__(256) void attn_kernel() {
    extern __shared__ float sm[];
    float* Qs = sm;            // [d][qrow]  64*128
    float* Ks = sm + 8192;     // [d][kcol]  64*128
    float* Vs = sm + 16384;    // [krow][d]  128*64
    const int t = threadIdx.x;
    const int tx = t & 15, ty = t >> 4;
    const int bh = blockIdx.z * HH + blockIdx.y;
    const int q0 = blockIdx.x * 128;
    const float* __restrict__ Qg = g_q + (size_t)bh * DD * NN;
    const float* __restrict__ Kg = g_k + (size_t)bh * DD * NN;
    const float* __restrict__ Vg = g_v + (size_t)bh * NN * DD;

    float4* Qs4 = (float4*)Qs;
    float4* Ks4 = (float4*)Ks;
    float4* Vs4 = (float4*)Vs;

    // Load Q tile: Qs[d][r] = Qg[d*NN + q0 + r], float4 along r.
#pragma unroll
    for (int i = 0; i < 8; i++) {
        int idx4 = t + i * 256;            // 0..2047
        int d = idx4 >> 5, r4 = idx4 & 31;
        Qs4[idx4] = *(const float4*)&Qg[(size_t)d * NN + q0 + r4 * 4];
    }

    float O[8][4] = {};
    float m_run[8], l_run[8];
#pragma unroll
    for (int i = 0; i < 8; i++) { m_run[i] = -1e30f; l_run[i] = 0.f; }

    for (int k0 = 0; k0 < NN; k0 += 128) {
        __syncthreads();
#pragma unroll
        for (int i = 0; i < 8; i++) {
            int idx4 = t + i * 256;
            int d = idx4 >> 5, c4 = idx4 & 31;
            Ks4[idx4] = *(const float4*)&Kg[(size_t)d * NN + k0 + c4 * 4];
            Vs4[idx4] = *(const float4*)&Vg[(size_t)k0 * DD + idx4 * 4];
        }
        __syncthreads();

        // S = Q K^T (128x128), 8x8 per thread
        float s[8][8] = {};
#pragma unroll 8
        for (int d = 0; d < DD; d++) {
            float4 a0 = Qs4[d * 32 + ty * 2];
            float4 a1 = Qs4[d * 32 + ty * 2 + 1];
            float4 b0 = Ks4[d * 32 + tx * 2];
            float4 b1 = Ks4[d * 32 + tx * 2 + 1];
            float aa[8] = {a0.x, a0.y, a0.z, a0.w, a1.x, a1.y, a1.z, a1.w};
            float bb[8] = {b0.x, b0.y, b0.z, b0.w, b1.x, b1.y, b1.z, b1.w};
#pragma unroll
            for (int i = 0; i < 8; i++)
#pragma unroll
                for (int j = 0; j < 8; j++) s[i][j] += aa[i] * bb[j];
        }

        // Online softmax per row (row owned by 16 lanes = same ty)
#pragma unroll
        for (int i = 0; i < 8; i++) {
            float mx = -1e30f;
#pragma unroll
            for (int j = 0; j < 8; j++) { s[i][j] *= SCALE_F; mx = fmaxf(mx, s[i][j]); }
#pragma unroll
            for (int off = 1; off < 16; off <<= 1)
                mx = fmaxf(mx, __shfl_xor_sync(0xffffffffu, mx, off, 16));
            float mnew = fmaxf(m_run[i], mx);
            float corr = __expf(m_run[i] - mnew);
            float rs = 0.f;
#pragma unroll
            for (int j = 0; j < 8; j++) {
                s[i][j] = __expf(s[i][j] - mnew);   // s becomes P
                rs += s[i][j];
            }
#pragma unroll
            for (int off = 1; off < 16; off <<= 1)
                rs += __shfl_xor_sync(0xffffffffu, rs, off, 16);
            l_run[i] = l_run[i] * corr + rs;
            m_run[i] = mnew;
#pragma unroll
            for (int j = 0; j < 4; j++) O[i][j] *= corr;
        }

        // O += P @ V.  P[i][kk] broadcast from owning lane (src = kk>>3).
#pragma unroll 8
        for (int kk = 0; kk < 128; kk++) {
            float4 v = Vs4[kk * 16 + tx];
            int src = kk >> 3;
            float vv[4] = {v.x, v.y, v.z, v.w};
#pragma unroll
            for (int i = 0; i < 8; i++) {
                float pv = __shfl_sync(0xffffffffu, s[i][kk & 7], src, 16);
#pragma unroll
                for (int j = 0; j < 4; j++) O[i][j] += pv * vv[j];
            }
        }
    }

    // Write O / l to g_att[b, n, h*64 + tx*4 ..]
    const int b = blockIdx.z;
    const int h = blockIdx.y;
#pragma unroll
    for (int i = 0; i < 8; i++) {
        int n = q0 + ty * 8 + i;
        float inv = 1.0f / l_run[i];
        *(float4*)(g_att + ((size_t)(b * NN + n)) * CC + h * DD + tx * 4) =
            make_float4(O[i][0] * inv, O[i][1] * inv, O[i][2] * inv, O[i][3] * inv);
    }
}

// ---------------------------------------------------------------------------
// Proj GEMM: out[r][c] = sum_k att[r][k] * w_proj[c][k] + b_proj[c]
// Same 128x128x8 / 8x8 structure.
// ---------------------------------------------------------------------------
__global__ __launch_bounds__(256) void proj_kernel(const float* __restrict__ w,
                                                   const float* __restrict__ bias,
                                                   float* __restrict__ out) {
    __shared__ float As[8][132];
    __shared__ float Bs[8][132];
    const int t = threadIdx.x;
    const int tx = t & 15, ty = t >> 4;
    const int row0 = blockIdx.y * 128;
    const int col0 = blockIdx.x * 128;
    const int lr = t >> 1;
    const int lc = (t & 1) * 4;
    float acc[8][8] = {};
    const float4* As4 = (const float4*)&As[0][0];
    const float4* Bs4 = (const float4*)&Bs[0][0];

    for (int k0 = 0; k0 < CC; k0 += 8) {
        __syncthreads();
        float4 av = *(const float4*)&g_att[(size_t)(row0 + lr) * CC + k0 + lc];
        float4 bv = *(const float4*)&w[(size_t)(col0 + lr) * CC + k0 + lc];
        As[lc + 0][lr] = av.x; As[lc + 1][lr] = av.y;
        As[lc + 2][lr] = av.z; As[lc + 3][lr] = av.w;
        Bs[lc + 0][lr] = bv.x; Bs[lc + 1][lr] = bv.y;
        Bs[lc + 2][lr] = bv.z; Bs[lc + 3][lr] = bv.w;
        __syncthreads();
#pragma unroll
        for (int kk = 0; kk < 8; kk++) {
            float4 a0 = As4[kk * 33 + ty * 2];
            float4 a1 = As4[kk * 33 + ty * 2 + 1];
            float4 b0 = Bs4[kk * 33 + tx * 2];
            float4 b1 = Bs4[kk * 33 + tx * 2 + 1];
            float aa[8] = {a0.x, a0.y, a0.z, a0.w, a1.x, a1.y, a1.z, a1.w};
            float bb[8] = {b0.x, b0.y, b0.z, b0.w, b1.x, b1.y, b1.z, b1.w};
#pragma unroll
            for (int i = 0; i < 8; i++)
#pragma unroll
                for (int j = 0; j < 8; j++) acc[i][j] += aa[i] * bb[j];
        }
    }

    const int c0 = col0 + tx * 8;
    float4 bz0 = *(const float4*)&bias[c0];
    float4 bz1 = *(const float4*)&bias[c0 + 4];
#pragma unroll
    for (int i = 0; i < 8; i++) {
        int r = row0 + ty * 8 + i;
        *(float4*)(out + (size_t)r * CC + c0) =
            make_float4(acc[i][0] + bz0.x, acc[i][1] + bz0.y,
                        acc[i][2] + bz0.z, acc[i][3] + bz0.w);
        *(float4*)(out + (size_t)r * CC + c0 + 4) =
            make_float4(acc[i][4] + bz1.x, acc[i][5] + bz1.y,
                        acc[i][6] + bz1.z, acc[i][7] + bz1.w);
    }
}

// ---------------------------------------------------------------------------
extern "C" void kernel_launch(void* const* d_in, const int* in_sizes, int n_in,
                              void* d_out, int out_size) {
    const float* x      = (const float*)d_in[0];
    const float* w_qkv  = (const float*)d_in[1];
    const float* w_proj = (const float*)d_in[2];
    const float* b_proj = (const float*)d_in[3];
    float* out = (float*)d_out;

    cudaFuncSetAttribute(attn_kernel,
                         cudaFuncAttributeMaxDynamicSharedMemorySize, 98304);

    dim3 g1(3 * CC / 128, MM / 128);        // 24 x 32
    qkv_kernel<<<g1, 256>>>(x, w_qkv);

    dim3 g2(NN / 128, HH, BB);              // 16 x 16 x 2
    attn_kernel<<<g2, 256, 98304>>>();

    dim3 g3(CC / 128, MM / 128);            // 8 x 32
    proj_kernel<<<g3, 256>>>(w_proj, b_proj, out);
}

// round 6
// speedup vs baseline: 1.3659x; 1.2821x over previous
#include <cuda_runtime.h>
#include <cuda_bf16.h>
#include <cstdint>

// MultiHeadAttention: B=2, N=2048, C=1024, H=16, D=64, fp32.
// R5: qkv + proj GEMMs on mma.sync bf16 (hi/lo split x3 -> ~fp32 accuracy).
//     (tcgen05 rejected: harness compiles PTX for compute_100, not 100a.)
//     attn stays the R3 SIMT flash-attention kernel (unchanged, known-good).

#define BB 2
#define NN 2048
#define CC 1024
#define HH 16
#define DD 64
#define MM (BB * NN)          // 4096
#define SCALE_F 0.125f

#define BKC 32                // k elems per chunk
#define NCH (CC / BKC)        // 32
#define AST 18                // smem stride in b32 words (36 bf16)
#define TW (128 * AST)        // words per tile: 2304
#define SMEM_GEMM (2 * 4 * TW * 4)   // 73728 bytes

__device__ float g_q[(size_t)BB * HH * DD * NN];   // [B,H,D,N]
__device__ float g_k[(size_t)BB * HH * DD * NN];   // [B,H,D,N]
__device__ float g_v[(size_t)BB * HH * NN * DD];   // [B,H,N,D]
__device__ float g_att[(size_t)MM * CC];           // [B,N,C]

extern __shared__ unsigned char dynsm[];

// ---------------------------------------------------------------------------
static __device__ __forceinline__ void mma16816(float* d, const uint32_t a[4],
                                                const uint32_t b[2]) {
    asm volatile(
        "mma.sync.aligned.m16n8k16.row.col.f32.bf16.bf16.f32 "
        "{%0,%1,%2,%3}, {%4,%5,%6,%7}, {%8,%9}, {%0,%1,%2,%3};"
        : "+f"(d[0]), "+f"(d[1]), "+f"(d[2]), "+f"(d[3])
        : "r"(a[0]), "r"(a[1]), "r"(a[2]), "r"(a[3]), "r"(b[0]), "r"(b[1]));
}

struct Stage { float4 a[4]; float4 b[4]; };

static __device__ __forceinline__ void load_stage(Stage& s,
                                                  const float* __restrict__ A,
                                                  const float* __restrict__ B,
                                                  int row0, int col0, int k0, int t) {
    const int lrow = t >> 1, lcol = (t & 1) * 16;
    const float4* pa = (const float4*)(A + (size_t)(row0 + lrow) * CC + k0 + lcol);
    const float4* pb = (const float4*)(B + (size_t)(col0 + lrow) * CC + k0 + lcol);
#pragma unroll
    for (int i = 0; i < 4; i++) { s.a[i] = pa[i]; s.b[i] = pb[i]; }
}

// 16 floats -> 8 hi words + 8 lo words at widx..+7
static __device__ __forceinline__ void cvt_store(const float4* v, uint32_t* hi,
                                                 uint32_t* lo, int widx) {
#pragma unroll
    for (int i = 0; i < 4; i++) {
        float f[4] = {v[i].x, v[i].y, v[i].z, v[i].w};
#pragma unroll
        for (int j = 0; j < 2; j++) {
            float x0 = f[2 * j], x1 = f[2 * j + 1];
            __nv_bfloat16 h0 = __float2bfloat16(x0);
            __nv_bfloat16 h1 = __float2bfloat16(x1);
            float l0 = x0 - __bfloat162float(h0);
            float l1 = x1 - __bfloat162float(h1);
            __nv_bfloat162 hp = __halves2bfloat162(h0, h1);
            __nv_bfloat162 lp = __halves2bfloat162(__float2bfloat16(l0),
                                                   __float2bfloat16(l1));
            hi[widx + i * 2 + j] = *(uint32_t*)&hp;
            lo[widx + i * 2 + j] = *(uint32_t*)&lp;
        }
    }
}

// 3-pass bf16x3 compute on one BK=32 chunk resident in smem buffer `buf`.
static __device__ __forceinline__ void compute_chunk(const uint32_t* sw, int buf,
                                                     float acc[2][8][4],
                                                     int wm, int wn, int lane) {
    const int lr = lane >> 2, lc2 = lane & 3;
    const uint32_t* base = sw + buf * 4 * TW;
    const uint32_t* pa[3] = {base, base, base + TW};
    const uint32_t* pb[3] = {base + 2 * TW, base + 3 * TW, base + 2 * TW};
#pragma unroll
    for (int p = 0; p < 3; p++) {
#pragma unroll
        for (int k16 = 0; k16 < 2; k16++) {
            const int kb = k16 * 8 + lc2;
            uint32_t af[2][4];
#pragma unroll
            for (int mf = 0; mf < 2; mf++) {
                const int r = wm * 32 + mf * 16 + lr;
                af[mf][0] = pa[p][r * AST + kb];
                af[mf][1] = pa[p][(r + 8) * AST + kb];
                af[mf][2] = pa[p][r * AST + kb + 4];
                af[mf][3] = pa[p][(r + 8) * AST + kb + 4];
            }
#pragma unroll
            for (int nf = 0; nf < 8; nf++) {
                const int n = wn * 64 + nf * 8 + lr;
                uint32_t bf[2];
                bf[0] = pb[p][n * AST + kb];
                bf[1] = pb[p][n * AST + kb + 4];
                mma16816(acc[0][nf], af[0], bf);
                mma16816(acc[1][nf], af[1], bf);
            }
        }
    }
}

// Mainloop: acc = A[row0:+128,:] @ B[col0:+128,:]^T  (both [*,CC] row-major)
static __device__ __forceinline__ void gemm_main(const float* __restrict__ A,
                                                 const float* __restrict__ B,
                                                 int row0, int col0,
                                                 float acc[2][8][4]) {
    uint32_t* sw = (uint32_t*)dynsm;
    const int t = threadIdx.x;
    const int wid = t >> 5, lane = t & 31;
    const int wm = wid & 3, wn = wid >> 2;
    const int widx = (t >> 1) * AST + (t & 1) * 8;

    Stage st;
    load_stage(st, A, B, row0, col0, 0, t);
    cvt_store(st.a, sw, sw + TW, widx);
    cvt_store(st.b, sw + 2 * TW, sw + 3 * TW, widx);
    __syncthreads();

    for (int c = 0; c < NCH; c++) {
        const bool more = (c + 1 < NCH);
        if (more) load_stage(st, A, B, row0, col0, (c + 1) * BKC, t);
        compute_chunk(sw, c & 1, acc, wm, wn, lane);
        if (more) {
            __syncthreads();
            uint32_t* d = sw + ((c + 1) & 1) * 4 * TW;
            cvt_store(st.a, d, d + TW, widx);
            cvt_store(st.b, d + 2 * TW, d + 3 * TW, widx);
            __syncthreads();
        }
    }
}

// ---------------------------------------------------------------------------
// qkv: [4096,3072] = x @ w_qkv^T -> scatter Q[B,H,D,N] K[B,H,D,N] V[B,H,N,D]
// ---------------------------------------------------------------------------
__global__ __launch_bounds__(256) void qkv_mma(const float* __restrict__ x,
                                               const float* __restrict__ w) {
    const int row0 = blockIdx.y * 128;
    const int col0 = blockIdx.x * 128;
    float acc[2][8][4] = {};
    gemm_main(x, w, row0, col0, acc);

    const int t = threadIdx.x, wid = t >> 5, lane = t & 31;
    const int wm = wid & 3, wn = wid >> 2;
    const int lr = lane >> 2, lc2 = lane & 3;
    const int which = col0 >> 10;                 // 0=Q 1=K 2=V
    const int colrem0 = (col0 & (CC - 1)) + wn * 64;
#pragma unroll
    for (int mf = 0; mf < 2; mf++) {
        const int rbase = row0 + wm * 32 + mf * 16 + lr;
#pragma unroll
        for (int half = 0; half < 2; half++) {
            const int r = rbase + half * 8;
            const int b = r >> 11, n = r & (NN - 1);
#pragma unroll
            for (int nf = 0; nf < 8; nf++) {
                const int c = colrem0 + nf * 8 + lc2 * 2;
                const float v0 = acc[mf][nf][half * 2];
                const float v1 = acc[mf][nf][half * 2 + 1];
                const int h = c >> 6, d = c & 63;
                if (which == 2) {
                    *(float2*)(g_v + ((size_t)(b * HH + h) * NN + n) * DD + d) =
                        make_float2(v0, v1);
                } else {
                    float* g = which ? g_k : g_q;
                    g[((size_t)((b * HH + h) * DD + d)) * NN + n] = v0;
                    g[((size_t)((b * HH + h) * DD + d + 1)) * NN + n] = v1;
                }
            }
        }
    }
}

// ---------------------------------------------------------------------------
// proj: out[4096,1024] = g_att @ w_proj^T + bias
// ---------------------------------------------------------------------------
__global__ __launch_bounds__(256) void proj_mma(const float* __restrict__ w,
                                                const float* __restrict__ bias,
                                                float* __restrict__ out) {
    const int row0 = blockIdx.y * 128;
    const int col0 = blockIdx.x * 128;
    float acc[2][8][4] = {};
    gemm_main(g_att, w, row0, col0, acc);

    const int t = threadIdx.x, wid = t >> 5, lane = t & 31;
    const int wm = wid & 3, wn = wid >> 2;
    const int lr = lane >> 2, lc2 = lane & 3;
#pragma unroll
    for (int mf = 0; mf < 2; mf++) {
        const int rbase = row0 + wm * 32 + mf * 16 + lr;
#pragma unroll
        for (int half = 0; half < 2; half++) {
            const int r = rbase + half * 8;
#pragma unroll
            for (int nf = 0; nf < 8; nf++) {
                const int c = col0 + wn * 64 + nf * 8 + lc2 * 2;
                *(float2*)(out + (size_t)r * CC + c) =
                    make_float2(acc[mf][nf][half * 2] + bias[c],
                                acc[mf][nf][half * 2 + 1] + bias[c + 1]);
            }
        }
    }
}

// ---------------------------------------------------------------------------
// Flash attention (unchanged from R3, known-good).
// ---------------------------------------------------------------------------
__global__ __launch_bounds__(256) void attn_kernel() {
    float* smf = (float*)dynsm;
    float* Qs = smf;
    float* Ks = smf + 8192;
    float* Vs = smf + 16384;
    const int t = threadIdx.x;
    const int tx = t & 15, ty = t >> 4;
    const int bh = blockIdx.z * HH + blockIdx.y;
    const int q0 = blockIdx.x * 128;
    const float* __restrict__ Qg = g_q + (size_t)bh * DD * NN;
    const float* __restrict__ Kg = g_k + (size_t)bh * DD * NN;
    const float* __restrict__ Vg = g_v + (size_t)bh * NN * DD;

    float4* Qs4 = (float4*)Qs;
    float4* Ks4 = (float4*)Ks;
    float4* Vs4 = (float4*)Vs;

#pragma unroll
    for (int i = 0; i < 8; i++) {
        int idx4 = t + i * 256;
        int d = idx4 >> 5, r4 = idx4 & 31;
        Qs4[idx4] = *(const float4*)&Qg[(size_t)d * NN + q0 + r4 * 4];
    }

    float O[8][4] = {};
    float m_run[8], l_run[8];
#pragma unroll
    for (int i = 0; i < 8; i++) { m_run[i] = -1e30f; l_run[i] = 0.f; }

    for (int k0 = 0; k0 < NN; k0 += 128) {
        __syncthreads();
#pragma unroll
        for (int i = 0; i < 8; i++) {
            int idx4 = t + i * 256;
            int d = idx4 >> 5, c4 = idx4 & 31;
            Ks4[idx4] = *(const float4*)&Kg[(size_t)d * NN + k0 + c4 * 4];
            Vs4[idx4] = *(const float4*)&Vg[(size_t)k0 * DD + idx4 * 4];
        }
        __syncthreads();

        float s[8][8] = {};
#pragma unroll 8
        for (int d = 0; d < DD; d++) {
            float4 a0 = Qs4[d * 32 + ty * 2];
            float4 a1 = Qs4[d * 32 + ty * 2 + 1];
            float4 b0 = Ks4[d * 32 + tx * 2];
            float4 b1 = Ks4[d * 32 + tx * 2 + 1];
            float aa[8] = {a0.x, a0.y, a0.z, a0.w, a1.x, a1.y, a1.z, a1.w};
            float bb[8] = {b0.x, b0.y, b0.z, b0.w, b1.x, b1.y, b1.z, b1.w};
#pragma unroll
            for (int i = 0; i < 8; i++)
#pragma unroll
                for (int j = 0; j < 8; j++) s[i][j] += aa[i] * bb[j];
        }

#pragma unroll
        for (int i = 0; i < 8; i++) {
            float mx = -1e30f;
#pragma unroll
            for (int j = 0; j < 8; j++) { s[i][j] *= SCALE_F; mx = fmaxf(mx, s[i][j]); }
#pragma unroll
            for (int off = 1; off < 16; off <<= 1)
                mx = fmaxf(mx, __shfl_xor_sync(0xffffffffu, mx, off, 16));
            float mnew = fmaxf(m_run[i], mx);
            float corr = __expf(m_run[i] - mnew);
            float rs = 0.f;
#pragma unroll
            for (int j = 0; j < 8; j++) {
                s[i][j] = __expf(s[i][j] - mnew);
                rs += s[i][j];
            }
#pragma unroll
            for (int off = 1; off < 16; off <<= 1)
                rs += __shfl_xor_sync(0xffffffffu, rs, off, 16);
            l_run[i] = l_run[i] * corr + rs;
            m_run[i] = mnew;
#pragma unroll
            for (int j = 0; j < 4; j++) O[i][j] *= corr;
        }

#pragma unroll 8
        for (int kk = 0; kk < 128; kk++) {
            float4 v = Vs4[kk * 16 + tx];
            int src = kk >> 3;
            float vv[4] = {v.x, v.y, v.z, v.w};
#pragma unroll
            for (int i = 0; i < 8; i++) {
                float pv = __shfl_sync(0xffffffffu, s[i][kk & 7], src, 16);
#pragma unroll
                for (int j = 0; j < 4; j++) O[i][j] += pv * vv[j];
            }
        }
    }

    const int b = blockIdx.z;
    const int h = blockIdx.y;
#pragma unroll
    for (int i = 0; i < 8; i++) {
        int n = q0 + ty * 8 + i;
        float inv = 1.0f / l_run[i];
        *(float4*)(g_att + ((size_t)(b * NN + n)) * CC + h * DD + tx * 4) =
            make_float4(O[i][0] * inv, O[i][1] * inv, O[i][2] * inv, O[i][3] * inv);
    }
}

// ---------------------------------------------------------------------------
extern "C" void kernel_launch(void* const* d_in, const int* in_sizes, int n_in,
                              void* d_out, int out_size) {
    const float* x      = (const float*)d_in[0];
    const float* w_qkv  = (const float*)d_in[1];
    const float* w_proj = (const float*)d_in[2];
    const float* b_proj = (const float*)d_in[3];
    float* out = (float*)d_out;

    cudaFuncSetAttribute(qkv_mma,  cudaFuncAttributeMaxDynamicSharedMemorySize, SMEM_GEMM);
    cudaFuncSetAttribute(proj_mma, cudaFuncAttributeMaxDynamicSharedMemorySize, SMEM_GEMM);
    cudaFuncSetAttribute(attn_kernel, cudaFuncAttributeMaxDynamicSharedMemorySize, 98304);

    dim3 g1(3 * CC / 128, MM / 128);        // 24 x 32
    qkv_mma<<<g1, 256, SMEM_GEMM>>>(x, w_qkv);

    dim3 g2(NN / 128, HH, BB);              // 16 x 16 x 2
    attn_kernel<<<g2, 256, 98304>>>();

    dim3 g3(CC / 128, MM / 128);            // 8 x 32
    proj_mma<<<g3, 256, SMEM_GEMM>>>(w_proj, b_proj, out);
}

// round 7
// speedup vs baseline: 1.3675x; 1.0012x over previous
#include <cuda_runtime.h>
#include <cuda_bf16.h>
#include <cstdint>

// MultiHeadAttention: B=2, N=2048, C=1024, H=16, D=64, fp32.
// R5: qkv + proj GEMMs on mma.sync bf16 (hi/lo split x3 -> ~fp32 accuracy).
//     (tcgen05 rejected: harness compiles PTX for compute_100, not 100a.)
//     attn stays the R3 SIMT flash-attention kernel (unchanged, known-good).

#define BB 2
#define NN 2048
#define CC 1024
#define HH 16
#define DD 64
#define MM (BB * NN)          // 4096
#define SCALE_F 0.125f

#define BKC 32                // k elems per chunk
#define NCH (CC / BKC)        // 32
#define AST 18                // smem stride in b32 words (36 bf16)
#define TW (128 * AST)        // words per tile: 2304
#define SMEM_GEMM (2 * 4 * TW * 4)   // 73728 bytes

__device__ float g_q[(size_t)BB * HH * DD * NN];   // [B,H,D,N]
__device__ float g_k[(size_t)BB * HH * DD * NN];   // [B,H,D,N]
__device__ float g_v[(size_t)BB * HH * NN * DD];   // [B,H,N,D]
__device__ float g_att[(size_t)MM * CC];           // [B,N,C]

extern __shared__ unsigned char dynsm[];

// ---------------------------------------------------------------------------
static __device__ __forceinline__ void mma16816(float* d, const uint32_t a[4],
                                                const uint32_t b[2]) {
    asm volatile(
        "mma.sync.aligned.m16n8k16.row.col.f32.bf16.bf16.f32 "
        "{%0,%1,%2,%3}, {%4,%5,%6,%7}, {%8,%9}, {%0,%1,%2,%3};"
        : "+f"(d[0]), "+f"(d[1]), "+f"(d[2]), "+f"(d[3])
        : "r"(a[0]), "r"(a[1]), "r"(a[2]), "r"(a[3]), "r"(b[0]), "r"(b[1]));
}

struct Stage { float4 a[4]; float4 b[4]; };

static __device__ __forceinline__ void load_stage(Stage& s,
                                                  const float* __restrict__ A,
                                                  const float* __restrict__ B,
                                                  int row0, int col0, int k0, int t) {
    const int lrow = t >> 1, lcol = (t & 1) * 16;
    const float4* pa = (const float4*)(A + (size_t)(row0 + lrow) * CC + k0 + lcol);
    const float4* pb = (const float4*)(B + (size_t)(col0 + lrow) * CC + k0 + lcol);
#pragma unroll
    for (int i = 0; i < 4; i++) { s.a[i] = pa[i]; s.b[i] = pb[i]; }
}

// 16 floats -> 8 hi words + 8 lo words at widx..+7
static __device__ __forceinline__ void cvt_store(const float4* v, uint32_t* hi,
                                                 uint32_t* lo, int widx) {
#pragma unroll
    for (int i = 0; i < 4; i++) {
        float f[4] = {v[i].x, v[i].y, v[i].z, v[i].w};
#pragma unroll
        for (int j = 0; j < 2; j++) {
            float x0 = f[2 * j], x1 = f[2 * j + 1];
            __nv_bfloat16 h0 = __float2bfloat16(x0);
            __nv_bfloat16 h1 = __float2bfloat16(x1);
            float l0 = x0 - __bfloat162float(h0);
            float l1 = x1 - __bfloat162float(h1);
            __nv_bfloat162 hp = __halves2bfloat162(h0, h1);
            __nv_bfloat162 lp = __halves2bfloat162(__float2bfloat16(l0),
                                                   __float2bfloat16(l1));
            hi[widx + i * 2 + j] = *(uint32_t*)&hp;
            lo[widx + i * 2 + j] = *(uint32_t*)&lp;
        }
    }
}

// 3-pass bf16x3 compute on one BK=32 chunk resident in smem buffer `buf`.
static __device__ __forceinline__ void compute_chunk(const uint32_t* sw, int buf,
                                                     float acc[2][8][4],
                                                     int wm, int wn, int lane) {
    const int lr = lane >> 2, lc2 = lane & 3;
    const uint32_t* base = sw + buf * 4 * TW;
    const uint32_t* pa[3] = {base, base, base + TW};
    const uint32_t* pb[3] = {base + 2 * TW, base + 3 * TW, base + 2 * TW};
#pragma unroll
    for (int p = 0; p < 3; p++) {
#pragma unroll
        for (int k16 = 0; k16 < 2; k16++) {
            const int kb = k16 * 8 + lc2;
            uint32_t af[2][4];
#pragma unroll
            for (int mf = 0; mf < 2; mf++) {
                const int r = wm * 32 + mf * 16 + lr;
                af[mf][0] = pa[p][r * AST + kb];
                af[mf][1] = pa[p][(r + 8) * AST + kb];
                af[mf][2] = pa[p][r * AST + kb + 4];
                af[mf][3] = pa[p][(r + 8) * AST + kb + 4];
            }
#pragma unroll
            for (int nf = 0; nf < 8; nf++) {
                const int n = wn * 64 + nf * 8 + lr;
                uint32_t bf[2];
                bf[0] = pb[p][n * AST + kb];
                bf[1] = pb[p][n * AST + kb + 4];
                mma16816(acc[0][nf], af[0], bf);
                mma16816(acc[1][nf], af[1], bf);
            }
        }
    }
}

// Mainloop: acc = A[row0:+128,:] @ B[col0:+128,:]^T  (both [*,CC] row-major)
static __device__ __forceinline__ void gemm_main(const float* __restrict__ A,
                                                 const float* __restrict__ B,
                                                 int row0, int col0,
                                                 float acc[2][8][4]) {
    uint32_t* sw = (uint32_t*)dynsm;
    const int t = threadIdx.x;
    const int wid = t >> 5, lane = t & 31;
    const int wm = wid & 3, wn = wid >> 2;
    const int widx = (t >> 1) * AST + (t & 1) * 8;

    Stage st;
    load_stage(st, A, B, row0, col0, 0, t);
    cvt_store(st.a, sw, sw + TW, widx);
    cvt_store(st.b, sw + 2 * TW, sw + 3 * TW, widx);
    __syncthreads();

    for (int c = 0; c < NCH; c++) {
        const bool more = (c + 1 < NCH);
        if (more) load_stage(st, A, B, row0, col0, (c + 1) * BKC, t);
        compute_chunk(sw, c & 1, acc, wm, wn, lane);
        if (more) {
            __syncthreads();
            uint32_t* d = sw + ((c + 1) & 1) * 4 * TW;
            cvt_store(st.a, d, d + TW, widx);
            cvt_store(st.b, d + 2 * TW, d + 3 * TW, widx);
            __syncthreads();
        }
    }
}

// ---------------------------------------------------------------------------
// qkv: [4096,3072] = x @ w_qkv^T -> scatter Q[B,H,D,N] K[B,H,D,N] V[B,H,N,D]
// ---------------------------------------------------------------------------
__global__ __launch_bounds__(256) void qkv_mma(const float* __restrict__ x,
                                               const float* __restrict__ w) {
    const int row0 = blockIdx.y * 128;
    const int col0 = blockIdx.x * 128;
    float acc[2][8][4] = {};
    gemm_main(x, w, row0, col0, acc);

    const int t = threadIdx.x, wid = t >> 5, lane = t & 31;
    const int wm = wid & 3, wn = wid >> 2;
    const int lr = lane >> 2, lc2 = lane & 3;
    const int which = col0 >> 10;                 // 0=Q 1=K 2=V
    const int colrem0 = (col0 & (CC - 1)) + wn * 64;
#pragma unroll
    for (int mf = 0; mf < 2; mf++) {
        const int rbase = row0 + wm * 32 + mf * 16 + lr;
#pragma unroll
        for (int half = 0; half < 2; half++) {
            const int r = rbase + half * 8;
            const int b = r >> 11, n = r & (NN - 1);
#pragma unroll
            for (int nf = 0; nf < 8; nf++) {
                const int c = colrem0 + nf * 8 + lc2 * 2;
                const float v0 = acc[mf][nf][half * 2];
                const float v1 = acc[mf][nf][half * 2 + 1];
                const int h = c >> 6, d = c & 63;
                if (which == 2) {
                    *(float2*)(g_v + ((size_t)(b * HH + h) * NN + n) * DD + d) =
                        make_float2(v0, v1);
                } else {
                    float* g = which ? g_k : g_q;
                    g[((size_t)((b * HH + h) * DD + d)) * NN + n] = v0;
                    g[((size_t)((b * HH + h) * DD + d + 1)) * NN + n] = v1;
                }
            }
        }
    }
}

// ---------------------------------------------------------------------------
// proj: out[4096,1024] = g_att @ w_proj^T + bias
// ---------------------------------------------------------------------------
__global__ __launch_bounds__(256) void proj_mma(const float* __restrict__ w,
                                                const float* __restrict__ bias,
                                                float* __restrict__ out) {
    const int row0 = blockIdx.y * 128;
    const int col0 = blockIdx.x * 128;
    float acc[2][8][4] = {};
    gemm_main(g_att, w, row0, col0, acc);

    const int t = threadIdx.x, wid = t >> 5, lane = t & 31;
    const int wm = wid & 3, wn = wid >> 2;
    const int lr = lane >> 2, lc2 = lane & 3;
#pragma unroll
    for (int mf = 0; mf < 2; mf++) {
        const int rbase = row0 + wm * 32 + mf * 16 + lr;
#pragma unroll
        for (int half = 0; half < 2; half++) {
            const int r = rbase + half * 8;
#pragma unroll
            for (int nf = 0; nf < 8; nf++) {
                const int c = col0 + wn * 64 + nf * 8 + lc2 * 2;
                *(float2*)(out + (size_t)r * CC + c) =
                    make_float2(acc[mf][nf][half * 2] + bias[c],
                                acc[mf][nf][half * 2 + 1] + bias[c + 1]);
            }
        }
    }
}

// ---------------------------------------------------------------------------
// Flash attention (unchanged from R3, known-good).
// ---------------------------------------------------------------------------
__global__ __launch_bounds__(256) void attn_kernel() {
    float* smf = (float*)dynsm;
    float* Qs = smf;
    float* Ks = smf + 8192;
    float* Vs = smf + 16384;
    const int t = threadIdx.x;
    const int tx = t & 15, ty = t >> 4;
    const int bh = blockIdx.z * HH + blockIdx.y;
    const int q0 = blockIdx.x * 128;
    const float* __restrict__ Qg = g_q + (size_t)bh * DD * NN;
    const float* __restrict__ Kg = g_k + (size_t)bh * DD * NN;
    const float* __restrict__ Vg = g_v + (size_t)bh * NN * DD;

    float4* Qs4 = (float4*)Qs;
    float4* Ks4 = (float4*)Ks;
    float4* Vs4 = (float4*)Vs;

#pragma unroll
    for (int i = 0; i < 8; i++) {
        int idx4 = t + i * 256;
        int d = idx4 >> 5, r4 = idx4 & 31;
        Qs4[idx4] = *(const float4*)&Qg[(size_t)d * NN + q0 + r4 * 4];
    }

    float O[8][4] = {};
    float m_run[8], l_run[8];
#pragma unroll
    for (int i = 0; i < 8; i++) { m_run[i] = -1e30f; l_run[i] = 0.f; }

    for (int k0 = 0; k0 < NN; k0 += 128) {
        __syncthreads();
#pragma unroll
        for (int i = 0; i < 8; i++) {
            int idx4 = t + i * 256;
            int d = idx4 >> 5, c4 = idx4 & 31;
            Ks4[idx4] = *(const float4*)&Kg[(size_t)d * NN + k0 + c4 * 4];
            Vs4[idx4] = *(const float4*)&Vg[(size_t)k0 * DD + idx4 * 4];
        }
        __syncthreads();

        float s[8][8] = {};
#pragma unroll 8
        for (int d = 0; d < DD; d++) {
            float4 a0 = Qs4[d * 32 + ty * 2];
            float4 a1 = Qs4[d * 32 + ty * 2 + 1];
            float4 b0 = Ks4[d * 32 + tx * 2];
            float4 b1 = Ks4[d * 32 + tx * 2 + 1];
            float aa[8] = {a0.x, a0.y, a0.z, a0.w, a1.x, a1.y, a1.z, a1.w};
            float bb[8] = {b0.x, b0.y, b0.z, b0.w, b1.x, b1.y, b1.z, b1.w};
#pragma unroll
            for (int i = 0; i < 8; i++)
#pragma unroll
                for (int j = 0; j < 8; j++) s[i][j] += aa[i] * bb[j];
        }

#pragma unroll
        for (int i = 0; i < 8; i++) {
            float mx = -1e30f;
#pragma unroll
            for (int j = 0; j < 8; j++) { s[i][j] *= SCALE_F; mx = fmaxf(mx, s[i][j]); }
#pragma unroll
            for (int off = 1; off < 16; off <<= 1)
                mx = fmaxf(mx, __shfl_xor_sync(0xffffffffu, mx, off, 16));
            float mnew = fmaxf(m_run[i], mx);
            float corr = __expf(m_run[i] - mnew);
            float rs = 0.f;
#pragma unroll
            for (int j = 0; j < 8; j++) {
                s[i][j] = __expf(s[i][j] - mnew);
                rs += s[i][j];
            }
#pragma unroll
            for (int off = 1; off < 16; off <<= 1)
                rs += __shfl_xor_sync(0xffffffffu, rs, off, 16);
            l_run[i] = l_run[i] * corr + rs;
            m_run[i] = mnew;
#pragma unroll
            for (int j = 0; j < 4; j++) O[i][j] *= corr;
        }

#pragma unroll 8
        for (int kk = 0; kk < 128; kk++) {
            float4 v = Vs4[kk * 16 + tx];
            int src = kk >> 3;
            float vv[4] = {v.x, v.y, v.z, v.w};
#pragma unroll
            for (int i = 0; i < 8; i++) {
                float pv = __shfl_sync(0xffffffffu, s[i][kk & 7], src, 16);
#pragma unroll
                for (int j = 0; j < 4; j++) O[i][j] += pv * vv[j];
            }
        }
    }

    const int b = blockIdx.z;
    const int h = blockIdx.y;
#pragma unroll
    for (int i = 0; i < 8; i++) {
        int n = q0 + ty * 8 + i;
        float inv = 1.0f / l_run[i];
        *(float4*)(g_att + ((size_t)(b * NN + n)) * CC + h * DD + tx * 4) =
            make_float4(O[i][0] * inv, O[i][1] * inv, O[i][2] * inv, O[i][3] * inv);
    }
}

// ---------------------------------------------------------------------------
extern "C" void kernel_launch(void* const* d_in, const int* in_sizes, int n_in,
                              void* d_out, int out_size) {
    const float* x      = (const float*)d_in[0];
    const float* w_qkv  = (const float*)d_in[1];
    const float* w_proj = (const float*)d_in[2];
    const float* b_proj = (const float*)d_in[3];
    float* out = (float*)d_out;

    cudaFuncSetAttribute(qkv_mma,  cudaFuncAttributeMaxDynamicSharedMemorySize, SMEM_GEMM);
    cudaFuncSetAttribute(proj_mma, cudaFuncAttributeMaxDynamicSharedMemorySize, SMEM_GEMM);
    cudaFuncSetAttribute(attn_kernel, cudaFuncAttributeMaxDynamicSharedMemorySize, 98304);

    dim3 g1(3 * CC / 128, MM / 128);        // 24 x 32
    qkv_mma<<<g1, 256, SMEM_GEMM>>>(x, w_qkv);

    dim3 g2(NN / 128, HH, BB);              // 16 x 16 x 2
    attn_kernel<<<g2, 256, 98304>>>();

    dim3 g3(CC / 128, MM / 128);            // 8 x 32
    proj_mma<<<g3, 256, SMEM_GEMM>>>(w_proj, b_proj, out);
}

// round 9
// speedup vs baseline: 2.0054x; 1.4664x over previous
#include <cuda_runtime.h>
#include <cuda_bf16.h>
#include <cstdint>

// MultiHeadAttention: B=2, N=2048, C=1024, H=16, D=64, fp32.
// R8: ALL three stages on mma.sync bf16 hi/lo x3 (~fp32 accuracy).
//   qkv : GEMM -> writes Q,K [B,H,N,D] and V [B,H,D,N] as bf16 hi+lo (Q pre-scaled)
//   attn: FA2-style mma attention, warp-private softmax, P in registers
//   proj: unchanged R7 GEMM + bias

#define BB 2
#define NN 2048
#define CC 1024
#define HH 16
#define DD 64
#define MM (BB * NN)
#define SCALE_F 0.125f

#define BKC 32
#define NCH (CC / BKC)
#define AST 18
#define TW (128 * AST)
#define SMEM_GEMM (2 * 4 * TW * 4)     // 73728
#define SMEM_ATTN 65536                // Ksh/Ksl/Vsh/Vsl 16KB each

// bf16 hi/lo packed operand tensors (u32 = 2 bf16)
__device__ uint32_t g_qh[(size_t)BB * HH * NN * DD / 2];  // [B,H,N,D], pre-scaled
__device__ uint32_t g_ql[(size_t)BB * HH * NN * DD / 2];
__device__ uint32_t g_kh[(size_t)BB * HH * NN * DD / 2];  // [B,H,N,D]
__device__ uint32_t g_kl[(size_t)BB * HH * NN * DD / 2];
__device__ uint32_t g_vh[(size_t)BB * HH * DD * NN / 2];  // [B,H,D,N]
__device__ uint32_t g_vl[(size_t)BB * HH * DD * NN / 2];
__device__ float g_att[(size_t)MM * CC];                  // [B,N,C]

extern __shared__ unsigned char dynsm[];

// ---------------------------------------------------------------------------
static __device__ __forceinline__ void mma16816(float* d, const uint32_t a[4],
                                                const uint32_t b[2]) {
    asm volatile(
        "mma.sync.aligned.m16n8k16.row.col.f32.bf16.bf16.f32 "
        "{%0,%1,%2,%3}, {%4,%5,%6,%7}, {%8,%9}, {%0,%1,%2,%3};"
        : "+f"(d[0]), "+f"(d[1]), "+f"(d[2]), "+f"(d[3])
        : "r"(a[0]), "r"(a[1]), "r"(a[2]), "r"(a[3]), "r"(b[0]), "r"(b[1]));
}
static __device__ __forceinline__ uint32_t packbf(float x0, float x1) {
    __nv_bfloat162 p = __halves2bfloat162(__float2bfloat16(x0), __float2bfloat16(x1));
    return *(uint32_t*)&p;
}

// ============================ GEMM machinery (R7) ============================
struct Stage { float4 a[4]; float4 b[4]; };

static __device__ __forceinline__ void load_stage(Stage& s,
                                                  const float* __restrict__ A,
                                                  const float* __restrict__ B,
                                                  int row0, int col0, int k0, int t) {
    const int lrow = t >> 1, lcol = (t & 1) * 16;
    const float4* pa = (const float4*)(A + (size_t)(row0 + lrow) * CC + k0 + lcol);
    const float4* pb = (const float4*)(B + (size_t)(col0 + lrow) * CC + k0 + lcol);
#pragma unroll
    for (int i = 0; i < 4; i++) { s.a[i] = pa[i]; s.b[i] = pb[i]; }
}

static __device__ __forceinline__ void cvt_store(const float4* v, uint32_t* hi,
                                                 uint32_t* lo, int widx) {
#pragma unroll
    for (int i = 0; i < 4; i++) {
        float f[4] = {v[i].x, v[i].y, v[i].z, v[i].w};
#pragma unroll
        for (int j = 0; j < 2; j++) {
            float x0 = f[2 * j], x1 = f[2 * j + 1];
            __nv_bfloat16 h0 = __float2bfloat16(x0);
            __nv_bfloat16 h1 = __float2bfloat16(x1);
            hi[widx + i * 2 + j] = packbf(x0, x1);
            lo[widx + i * 2 + j] = packbf(x0 - __bfloat162float(h0),
                                          x1 - __bfloat162float(h1));
        }
    }
}

static __device__ __forceinline__ void compute_chunk(const uint32_t* sw, int buf,
                                                     float acc[2][8][4],
                                                     int wm, int wn, int lane) {
    const int lr = lane >> 2, lc2 = lane & 3;
    const uint32_t* base = sw + buf * 4 * TW;
    const uint32_t* pa[3] = {base, base, base + TW};
    const uint32_t* pb[3] = {base + 2 * TW, base + 3 * TW, base + 2 * TW};
#pragma unroll
    for (int p = 0; p < 3; p++) {
#pragma unroll
        for (int k16 = 0; k16 < 2; k16++) {
            const int kb = k16 * 8 + lc2;
            uint32_t af[2][4];
#pragma unroll
            for (int mf = 0; mf < 2; mf++) {
                const int r = wm * 32 + mf * 16 + lr;
                af[mf][0] = pa[p][r * AST + kb];
                af[mf][1] = pa[p][(r + 8) * AST + kb];
                af[mf][2] = pa[p][r * AST + kb + 4];
                af[mf][3] = pa[p][(r + 8) * AST + kb + 4];
            }
#pragma unroll
            for (int nf = 0; nf < 8; nf++) {
                const int n = wn * 64 + nf * 8 + lr;
                uint32_t bf[2];
                bf[0] = pb[p][n * AST + kb];
                bf[1] = pb[p][n * AST + kb + 4];
                mma16816(acc[0][nf], af[0], bf);
                mma16816(acc[1][nf], af[1], bf);
            }
        }
    }
}

static __device__ __forceinline__ void gemm_main(const float* __restrict__ A,
                                                 const float* __restrict__ B,
                                                 int row0, int col0,
                                                 float acc[2][8][4]) {
    uint32_t* sw = (uint32_t*)dynsm;
    const int t = threadIdx.x;
    const int wid = t >> 5, lane = t & 31;
    const int wm = wid & 3, wn = wid >> 2;
    const int widx = (t >> 1) * AST + (t & 1) * 8;

    Stage st;
    load_stage(st, A, B, row0, col0, 0, t);
    cvt_store(st.a, sw, sw + TW, widx);
    cvt_store(st.b, sw + 2 * TW, sw + 3 * TW, widx);
    __syncthreads();

    for (int c = 0; c < NCH; c++) {
        const bool more = (c + 1 < NCH);
        if (more) load_stage(st, A, B, row0, col0, (c + 1) * BKC, t);
        compute_chunk(sw, c & 1, acc, wm, wn, lane);
        if (more) {
            __syncthreads();
            uint32_t* d = sw + ((c + 1) & 1) * 4 * TW;
            cvt_store(st.a, d, d + TW, widx);
            cvt_store(st.b, d + 2 * TW, d + 3 * TW, widx);
            __syncthreads();
        }
    }
}

// ---------------------------------------------------------------------------
// qkv: [4096,3072] = x @ w_qkv^T -> bf16 hi/lo Q,K [B,H,N,D] (Q*0.125), V [B,H,D,N]
// ---------------------------------------------------------------------------
__global__ __launch_bounds__(256) void qkv_mma(const float* __restrict__ x,
                                               const float* __restrict__ w) {
    const int row0 = blockIdx.y * 128;
    const int col0 = blockIdx.x * 128;
    float acc[2][8][4] = {};
    gemm_main(x, w, row0, col0, acc);

    const int t = threadIdx.x, wid = t >> 5, lane = t & 31;
    const int wm = wid & 3, wn = wid >> 2;
    const int lr = lane >> 2, lc2 = lane & 3;
    const int which = col0 >> 10;                 // 0=Q 1=K 2=V
    const int colrem0 = (col0 & (CC - 1)) + wn * 64;
#pragma unroll
    for (int mf = 0; mf < 2; mf++) {
        const int rbase = row0 + wm * 32 + mf * 16 + lr;
#pragma unroll
        for (int half = 0; half < 2; half++) {
            const int r = rbase + half * 8;
            const int b = r >> 11, n = r & (NN - 1);
#pragma unroll
            for (int nf = 0; nf < 8; nf++) {
                const int c = colrem0 + nf * 8 + lc2 * 2;
                float v0 = acc[mf][nf][half * 2];
                float v1 = acc[mf][nf][half * 2 + 1];
                const int h = c >> 6, d = c & 63;
                if (which == 0) { v0 *= SCALE_F; v1 *= SCALE_F; }
                __nv_bfloat16 h0 = __float2bfloat16(v0);
                __nv_bfloat16 h1 = __float2bfloat16(v1);
                __nv_bfloat16 e0 = __float2bfloat16(v0 - __bfloat162float(h0));
                __nv_bfloat16 e1 = __float2bfloat16(v1 - __bfloat162float(h1));
                if (which == 2) {
                    size_t base = ((size_t)(b * HH + h) * DD + d) * NN + n;
                    __nv_bfloat16* vh = (__nv_bfloat16*)g_vh;
                    __nv_bfloat16* vl = (__nv_bfloat16*)g_vl;
                    vh[base] = h0; vh[base + NN] = h1;
                    vl[base] = e0; vl[base + NN] = e1;
                } else {
                    __nv_bfloat162 hp = __halves2bfloat162(h0, h1);
                    __nv_bfloat162 lp = __halves2bfloat162(e0, e1);
                    uint32_t* ah = which ? g_kh : g_qh;
                    uint32_t* al = which ? g_kl : g_ql;
                    size_t idx = ((size_t)(b * HH + h) * NN + n) * 32 + (d >> 1);
                    ah[idx] = *(uint32_t*)&hp;
                    al[idx] = *(uint32_t*)&lp;
                }
            }
        }
    }
}

// ---------------------------------------------------------------------------
// Attention on mma.sync. Block = 128 q of one (b,h), 8 warps x 16 q-rows.
// Per iter: 128 keys. Smem: Ksh/Ksl [128][32u32], Vsh/Vsl [64][64u32],
// XOR-swizzled (u32 col c at row r stored at c ^ ((r&7)<<2)).
// ---------------------------------------------------------------------------
__global__ __launch_bounds__(256) void attn_mma() {
    uint32_t* Ksh = (uint32_t*)dynsm;          // 4096 u32
    uint32_t* Ksl = Ksh + 4096;
    uint32_t* Vsh = Ksl + 4096;                // 4096 u32
    uint32_t* Vsl = Vsh + 4096;
    const int t = threadIdx.x, wid = t >> 5, lane = t & 31;
    const int lr = lane >> 2, lc2 = lane & 3;
    const int bh = blockIdx.z * HH + blockIdx.y;
    const int q0 = blockIdx.x * 128;

    // Q fragments straight from gmem (hi & lo), rows wid*16+lr / +8
    uint32_t qh[4][4], ql[4][4];
    {
        const size_t rbase = ((size_t)bh * NN + q0 + wid * 16) * 32;
        const uint32_t* r0h = g_qh + rbase + (size_t)lr * 32;
        const uint32_t* r1h = r0h + 8 * 32;
        const uint32_t* r0l = g_ql + rbase + (size_t)lr * 32;
        const uint32_t* r1l = r0l + 8 * 32;
#pragma unroll
        for (int c = 0; c < 4; c++) {
            qh[c][0] = r0h[8 * c + lc2];     qh[c][1] = r1h[8 * c + lc2];
            qh[c][2] = r0h[8 * c + lc2 + 4]; qh[c][3] = r1h[8 * c + lc2 + 4];
            ql[c][0] = r0l[8 * c + lc2];     ql[c][1] = r1l[8 * c + lc2];
            ql[c][2] = r0l[8 * c + lc2 + 4]; ql[c][3] = r1l[8 * c + lc2 + 4];
        }
    }

    float o[8][4] = {};
    float m0 = -1e30f, m1 = -1e30f, l0 = 0.f, l1 = 0.f;

    const uint4* gkh = (const uint4*)g_kh + ((size_t)bh * NN) * 8;
    const uint4* gkl = (const uint4*)g_kl + ((size_t)bh * NN) * 8;
    const uint4* gvh = (const uint4*)g_vh + ((size_t)bh * DD) * 256;
    const uint4* gvl = (const uint4*)g_vl + ((size_t)bh * DD) * 256;

    for (int k0 = 0; k0 < NN; k0 += 128) {
        __syncthreads();
        // fill K (128 rows x 8 uint4) and V (64 rows x 16 uint4), swizzled
#pragma unroll
        for (int i = 0; i < 4; i++) {
            int idx = t + i * 256;
            int key = idx >> 3, c4 = idx & 7;
            int dst = key * 8 + (c4 ^ (key & 7));
            ((uint4*)Ksh)[dst] = gkh[(size_t)(k0 + key) * 8 + c4];
            ((uint4*)Ksl)[dst] = gkl[(size_t)(k0 + key) * 8 + c4];
            int d = idx >> 4, v4 = idx & 15;
            int vdst = d * 16 + (v4 ^ (d & 7));
            ((uint4*)Vsh)[vdst] = gvh[(size_t)d * 256 + (k0 >> 3) + v4];
            ((uint4*)Vsl)[vdst] = gvl[(size_t)d * 256 + (k0 >> 3) + v4];
        }
        __syncthreads();

        // S = Q K^T : 16 n8-tiles per warp, 4 k16 chunks, 3 passes
        float s[16][4] = {};
        const int xr = lr << 2;
#pragma unroll
        for (int c = 0; c < 4; c++) {
            const int col0i = (8 * c + lc2) ^ xr;
#pragma unroll
            for (int t16 = 0; t16 < 16; t16++) {
                const int base = (8 * t16 + lr) * 32;
                uint32_t bh2[2] = {Ksh[base + col0i], Ksh[base + (col0i ^ 4)]};
                uint32_t bl2[2] = {Ksl[base + col0i], Ksl[base + (col0i ^ 4)]};
                mma16816(s[t16], qh[c], bh2);
                mma16816(s[t16], ql[c], bh2);
                mma16816(s[t16], qh[c], bl2);
            }
        }

        // online softmax: rows lr (s[][0..1]) and lr+8 (s[][2..3])
        float mx0 = -1e30f, mx1 = -1e30f;
#pragma unroll
        for (int t16 = 0; t16 < 16; t16++) {
            mx0 = fmaxf(mx0, fmaxf(s[t16][0], s[t16][1]));
            mx1 = fmaxf(mx1, fmaxf(s[t16][2], s[t16][3]));
        }
#pragma unroll
        for (int off = 1; off < 4; off <<= 1) {
            mx0 = fmaxf(mx0, __shfl_xor_sync(0xffffffffu, mx0, off));
            mx1 = fmaxf(mx1, __shfl_xor_sync(0xffffffffu, mx1, off));
        }
        float mn0 = fmaxf(m0, mx0), mn1 = fmaxf(m1, mx1);
        float cr0 = __expf(m0 - mn0), cr1 = __expf(m1 - mn1);
        float rs0 = 0.f, rs1 = 0.f;
#pragma unroll
        for (int t16 = 0; t16 < 16; t16++) {
            s[t16][0] = __expf(s[t16][0] - mn0);
            s[t16][1] = __expf(s[t16][1] - mn0);
            s[t16][2] = __expf(s[t16][2] - mn1);
            s[t16][3] = __expf(s[t16][3] - mn1);
            rs0 += s[t16][0] + s[t16][1];
            rs1 += s[t16][2] + s[t16][3];
        }
#pragma unroll
        for (int off = 1; off < 4; off <<= 1) {
            rs0 += __shfl_xor_sync(0xffffffffu, rs0, off);
            rs1 += __shfl_xor_sync(0xffffffffu, rs1, off);
        }
        l0 = l0 * cr0 + rs0; m0 = mn0;
        l1 = l1 * cr1 + rs1; m1 = mn1;
#pragma unroll
        for (int nf = 0; nf < 8; nf++) {
            o[nf][0] *= cr0; o[nf][1] *= cr0;
            o[nf][2] *= cr1; o[nf][3] *= cr1;
        }

        // O += P V : P (registers) hi/lo, 8 k16 chunks, 8 n8-tiles (d)
#pragma unroll
        for (int c = 0; c < 8; c++) {
            uint32_t ph[4], pl[4];
#pragma unroll
            for (int u = 0; u < 2; u++) {      // tiles 2c, 2c+1 -> a0/a1, a2/a3
                const float* sv = s[2 * c + u];
                ph[2 * u]     = packbf(sv[0], sv[1]);
                ph[2 * u + 1] = packbf(sv[2], sv[3]);
                __nv_bfloat162 hp0 = *(__nv_bfloat162*)&ph[2 * u];
                __nv_bfloat162 hp1 = *(__nv_bfloat162*)&ph[2 * u + 1];
                pl[2 * u]     = packbf(sv[0] - __low2float(hp0), sv[1] - __high2float(hp0));
                pl[2 * u + 1] = packbf(sv[2] - __low2float(hp1), sv[3] - __high2float(hp1));
            }
            const int vc0 = (8 * c + lc2) ^ xr;
#pragma unroll
            for (int nf = 0; nf < 8; nf++) {
                const int base = (8 * nf + lr) * 64;
                uint32_t vh2[2] = {Vsh[base + vc0], Vsh[base + (vc0 ^ 4)]};
                uint32_t vl2[2] = {Vsl[base + vc0], Vsl[base + (vc0 ^ 4)]};
                mma16816(o[nf], ph, vh2);
                mma16816(o[nf], pl, vh2);
                mma16816(o[nf], ph, vl2);
            }
        }
    }

    // epilogue -> g_att[b, n, h*64 + d]
    const int b = blockIdx.z, h = blockIdx.y;
    const float i0 = 1.0f / l0, i1 = 1.0f / l1;
    const int n0 = q0 + wid * 16 + lr;
#pragma unroll
    for (int nf = 0; nf < 8; nf++) {
        const int d = 8 * nf + 2 * lc2;
        *(float2*)(g_att + ((size_t)(b * NN + n0)) * CC + h * DD + d) =
            make_float2(o[nf][0] * i0, o[nf][1] * i0);
        *(float2*)(g_att + ((size_t)(b * NN + n0 + 8)) * CC + h * DD + d) =
            make_float2(o[nf][2] * i1, o[nf][3] * i1);
    }
}

// ---------------------------------------------------------------------------
// proj: out[4096,1024] = g_att @ w_proj^T + bias  (unchanged R7)
// ---------------------------------------------------------------------------
__global__ __launch_bounds__(256) void proj_mma(const float* __restrict__ w,
                                                const float* __restrict__ bias,
                                                float* __restrict__ out) {
    const int row0 = blockIdx.y * 128;
    const int col0 = blockIdx.x * 128;
    float acc[2][8][4] = {};
    gemm_main(g_att, w, row0, col0, acc);

    const int t = threadIdx.x, wid = t >> 5, lane = t & 31;
    const int wm = wid & 3, wn = wid >> 2;
    const int lr = lane >> 2, lc2 = lane & 3;
#pragma unroll
    for (int mf = 0; mf < 2; mf++) {
        const int rbase = row0 + wm * 32 + mf * 16 + lr;
#pragma unroll
        for (int half = 0; half < 2; half++) {
            const int r = rbase + half * 8;
#pragma unroll
            for (int nf = 0; nf < 8; nf++) {
                const int c = col0 + wn * 64 + nf * 8 + lc2 * 2;
                *(float2*)(out + (size_t)r * CC + c) =
                    make_float2(acc[mf][nf][half * 2] + bias[c],
                                acc[mf][nf][half * 2 + 1] + bias[c + 1]);
            }
        }
    }
}

// ---------------------------------------------------------------------------
extern "C" void kernel_launch(void* const* d_in, const int* in_sizes, int n_in,
                              void* d_out, int out_size) {
    const float* x      = (const float*)d_in[0];
    const float* w_qkv  = (const float*)d_in[1];
    const float* w_proj = (const float*)d_in[2];
    const float* b_proj = (const float*)d_in[3];
    float* out = (float*)d_out;

    cudaFuncSetAttribute(qkv_mma,  cudaFuncAttributeMaxDynamicSharedMemorySize, SMEM_GEMM);
    cudaFuncSetAttribute(proj_mma, cudaFuncAttributeMaxDynamicSharedMemorySize, SMEM_GEMM);
    cudaFuncSetAttribute(attn_mma, cudaFuncAttributeMaxDynamicSharedMemorySize, SMEM_ATTN);

    dim3 g1(3 * CC / 128, MM / 128);        // 24 x 32
    qkv_mma<<<g1, 256, SMEM_GEMM>>>(x, w_qkv);

    dim3 g2(NN / 128, HH, BB);              // 16 x 16 x 2
    attn_mma<<<g2, 256, SMEM_ATTN>>>();

    dim3 g3(CC / 128, MM / 128);            // 8 x 32
    proj_mma<<<g3, 256, SMEM_GEMM>>>(w_proj, b_proj, out);
}

// round 10
// speedup vs baseline: 2.6075x; 1.3002x over previous
#include <cuda_runtime.h>
#include <cuda_bf16.h>
#include <cstdint>

// MultiHeadAttention: B=2, N=2048, C=1024, H=16, D=64, fp32.
// R10: pre-convert everything to bf16 hi/lo once; GEMMs are pure-bf16
//      cp.async double-buffered mma pipelines; attn emits bf16 hi/lo O.

#define BB 2
#define NN 2048
#define CC 1024
#define HH 16
#define DD 64
#define MM (BB * NN)
#define SCALE_F 0.125f
#define CW (CC / 2)            // 512 u32 per row

#define NCH 32                 // k chunks (BK=32 elems = 16 u32)
#define SST 20                 // smem row stride, u32 (pad 16->20, conflict-free)
#define STW (128 * SST)        // u32 per tile = 2560
#define STW4 (STW * 4)         // bytes per tile
#define SMEM_GEMM (2 * 4 * STW4)   // 81920
#define SMEM_ATTN 65536

// ---- bf16 hi/lo packed tensors (u32 = 2 bf16) ----
__device__ uint32_t g_xh[(size_t)MM * CW],  g_xl[(size_t)MM * CW];
__device__ uint32_t g_wqh[(size_t)3 * CC * CW], g_wql[(size_t)3 * CC * CW];
__device__ uint32_t g_wph[(size_t)CC * CW], g_wpl[(size_t)CC * CW];
__device__ uint32_t g_qh[(size_t)BB * HH * NN * DD / 2], g_ql[(size_t)BB * HH * NN * DD / 2];
__device__ uint32_t g_kh[(size_t)BB * HH * NN * DD / 2], g_kl[(size_t)BB * HH * NN * DD / 2];
__device__ uint32_t g_vh[(size_t)BB * HH * DD * NN / 2], g_vl[(size_t)BB * HH * DD * NN / 2];
__device__ uint32_t g_atth[(size_t)MM * CW], g_attl[(size_t)MM * CW];

extern __shared__ unsigned char dynsm[];

// ---------------------------------------------------------------------------
static __device__ __forceinline__ void mma16816(float* d, const uint32_t a[4],
                                                const uint32_t b[2]) {
    asm volatile(
        "mma.sync.aligned.m16n8k16.row.col.f32.bf16.bf16.f32 "
        "{%0,%1,%2,%3}, {%4,%5,%6,%7}, {%8,%9}, {%0,%1,%2,%3};"
        : "+f"(d[0]), "+f"(d[1]), "+f"(d[2]), "+f"(d[3])
        : "r"(a[0]), "r"(a[1]), "r"(a[2]), "r"(a[3]), "r"(b[0]), "r"(b[1]));
}
static __device__ __forceinline__ uint32_t packbf(float x0, float x1) {
    __nv_bfloat162 p = __halves2bfloat162(__float2bfloat16(x0), __float2bfloat16(x1));
    return *(uint32_t*)&p;
}
static __device__ __forceinline__ void cpa16(uint32_t dst, const uint32_t* src) {
    asm volatile("cp.async.ca.shared.global [%0], [%1], 16;"
                 :: "r"(dst), "l"(src) : "memory");
}
#define CP_COMMIT() asm volatile("cp.async.commit_group;" ::: "memory")
#define CP_WAIT(n)  asm volatile("cp.async.wait_group %0;" :: "n"(n) : "memory")

// ---------------------------------------------------------------------------
// fp32 -> bf16 hi/lo conversion (elementwise, memory-bound)
// ---------------------------------------------------------------------------
__global__ __launch_bounds__(256) void cvt_hilo(const float* __restrict__ src,
                                                uint32_t* __restrict__ hi,
                                                uint32_t* __restrict__ lo, int n4) {
    int i = blockIdx.x * blockDim.x + threadIdx.x;
    if (i >= n4) return;
    float4 v = ((const float4*)src)[i];
    __nv_bfloat16 h0 = __float2bfloat16(v.x), h1 = __float2bfloat16(v.y);
    __nv_bfloat16 h2 = __float2bfloat16(v.z), h3 = __float2bfloat16(v.w);
    uint32_t hw0 = packbf(v.x, v.y), hw1 = packbf(v.z, v.w);
    uint32_t lw0 = packbf(v.x - __bfloat162float(h0), v.y - __bfloat162float(h1));
    uint32_t lw1 = packbf(v.z - __bfloat162float(h2), v.w - __bfloat162float(h3));
    ((uint2*)hi)[i] = make_uint2(hw0, hw1);
    ((uint2*)lo)[i] = make_uint2(lw0, lw1);
}

// ---------------------------------------------------------------------------
// Pure-bf16 GEMM mainloop: acc = A[row0:+128,:] @ B[col0:+128,:]^T
// A,B given as hi/lo u32 tensors [*, CW]. cp.async double-buffered.
// ---------------------------------------------------------------------------
static __device__ __forceinline__ void prefetch4(const uint32_t* __restrict__ Ah,
                                                 const uint32_t* __restrict__ Al,
                                                 const uint32_t* __restrict__ Bh,
                                                 const uint32_t* __restrict__ Bl,
                                                 int row0, int col0, int c,
                                                 uint32_t sbase, int t) {
#pragma unroll
    for (int i = 0; i < 2; i++) {
        int idx = t + i * 256;
        int row = idx >> 2, q = (idx & 3) * 4;
        uint32_t doff = (uint32_t)(row * SST + q) * 4u;
        size_t aoff = (size_t)(row0 + row) * CW + c * 16 + q;
        size_t boff = (size_t)(col0 + row) * CW + c * 16 + q;
        cpa16(sbase + doff,            Ah + aoff);
        cpa16(sbase + STW4 + doff,     Al + aoff);
        cpa16(sbase + 2 * STW4 + doff, Bh + boff);
        cpa16(sbase + 3 * STW4 + doff, Bl + boff);
    }
}

static __device__ __forceinline__ void bf16gemm(const uint32_t* __restrict__ Ah,
                                                const uint32_t* __restrict__ Al,
                                                const uint32_t* __restrict__ Bh,
                                                const uint32_t* __restrict__ Bl,
                                                int row0, int col0, float acc[2][8][4]) {
    const int t = threadIdx.x;
    const int wid = t >> 5, lane = t & 31;
    const int wm = wid & 3, wn = wid >> 2;
    const int lr = lane >> 2, lc2 = lane & 3;
    uint32_t* sw = (uint32_t*)dynsm;
    const uint32_t sb = (uint32_t)__cvta_generic_to_shared(dynsm);

    prefetch4(Ah, Al, Bh, Bl, row0, col0, 0, sb, t);
    CP_COMMIT();

    for (int c = 0; c < NCH; c++) {
        const int buf = c & 1;
        if (c + 1 < NCH) {
            prefetch4(Ah, Al, Bh, Bl, row0, col0, c + 1,
                      sb + (uint32_t)((c + 1) & 1) * 4 * STW4, t);
            CP_COMMIT();
            CP_WAIT(1);
        } else {
            CP_WAIT(0);
        }
        __syncthreads();

        const uint32_t* base = sw + buf * 4 * STW;
        const uint32_t* pa[3] = {base, base, base + STW};
        const uint32_t* pb[3] = {base + 2 * STW, base + 3 * STW, base + 2 * STW};
#pragma unroll
        for (int p = 0; p < 3; p++) {
#pragma unroll
            for (int k16 = 0; k16 < 2; k16++) {
                const int kb = k16 * 8 + lc2;
                uint32_t af[2][4];
#pragma unroll
                for (int mf = 0; mf < 2; mf++) {
                    const int r = wm * 32 + mf * 16 + lr;
                    af[mf][0] = pa[p][r * SST + kb];
                    af[mf][1] = pa[p][(r + 8) * SST + kb];
                    af[mf][2] = pa[p][r * SST + kb + 4];
                    af[mf][3] = pa[p][(r + 8) * SST + kb + 4];
                }
#pragma unroll
                for (int nf = 0; nf < 8; nf++) {
                    const int n = wn * 64 + nf * 8 + lr;
                    uint32_t bf2[2];
                    bf2[0] = pb[p][n * SST + kb];
                    bf2[1] = pb[p][n * SST + kb + 4];
                    mma16816(acc[0][nf], af[0], bf2);
                    mma16816(acc[1][nf], af[1], bf2);
                }
            }
        }
        __syncthreads();
    }
}

// ---------------------------------------------------------------------------
// qkv: x @ w_qkv^T -> Q,K [B,H,N,D] hi/lo (Q pre-scaled), V [B,H,D,N] hi/lo
// ---------------------------------------------------------------------------
__global__ __launch_bounds__(256, 2) void qkv_mma() {
    const int row0 = blockIdx.y * 128;
    const int col0 = blockIdx.x * 128;
    float acc[2][8][4] = {};
    bf16gemm(g_xh, g_xl, g_wqh, g_wql, row0, col0, acc);

    const int t = threadIdx.x, wid = t >> 5, lane = t & 31;
    const int wm = wid & 3, wn = wid >> 2;
    const int lr = lane >> 2, lc2 = lane & 3;
    const int which = col0 >> 10;                 // 0=Q 1=K 2=V
    const int colrem0 = (col0 & (CC - 1)) + wn * 64;
#pragma unroll
    for (int mf = 0; mf < 2; mf++) {
        const int rbase = row0 + wm * 32 + mf * 16 + lr;
#pragma unroll
        for (int half = 0; half < 2; half++) {
            const int r = rbase + half * 8;
            const int b = r >> 11, n = r & (NN - 1);
#pragma unroll
            for (int nf = 0; nf < 8; nf++) {
                const int c = colrem0 + nf * 8 + lc2 * 2;
                float v0 = acc[mf][nf][half * 2];
                float v1 = acc[mf][nf][half * 2 + 1];
                const int h = c >> 6, d = c & 63;
                if (which == 0) { v0 *= SCALE_F; v1 *= SCALE_F; }
                __nv_bfloat16 h0 = __float2bfloat16(v0);
                __nv_bfloat16 h1 = __float2bfloat16(v1);
                __nv_bfloat16 e0 = __float2bfloat16(v0 - __bfloat162float(h0));
                __nv_bfloat16 e1 = __float2bfloat16(v1 - __bfloat162float(h1));
                if (which == 2) {
                    size_t base = ((size_t)(b * HH + h) * DD + d) * NN + n;
                    __nv_bfloat16* vh = (__nv_bfloat16*)g_vh;
                    __nv_bfloat16* vl = (__nv_bfloat16*)g_vl;
                    vh[base] = h0; vh[base + NN] = h1;
                    vl[base] = e0; vl[base + NN] = e1;
                } else {
                    __nv_bfloat162 hp = __halves2bfloat162(h0, h1);
                    __nv_bfloat162 lp = __halves2bfloat162(e0, e1);
                    uint32_t* ah = which ? g_kh : g_qh;
                    uint32_t* al = which ? g_kl : g_ql;
                    size_t idx = ((size_t)(b * HH + h) * NN + n) * 32 + (d >> 1);
                    ah[idx] = *(uint32_t*)&hp;
                    al[idx] = *(uint32_t*)&lp;
                }
            }
        }
    }
}

// ---------------------------------------------------------------------------
// Attention (R9 core, epilogue now emits bf16 hi/lo into g_atth/g_attl)
// ---------------------------------------------------------------------------
__global__ __launch_bounds__(256) void attn_mma() {
    uint32_t* Ksh = (uint32_t*)dynsm;
    uint32_t* Ksl = Ksh + 4096;
    uint32_t* Vsh = Ksl + 4096;
    uint32_t* Vsl = Vsh + 4096;
    const int t = threadIdx.x, wid = t >> 5, lane = t & 31;
    const int lr = lane >> 2, lc2 = lane & 3;
    const int bh = blockIdx.z * HH + blockIdx.y;
    const int q0 = blockIdx.x * 128;

    uint32_t qh[4][4], ql[4][4];
    {
        const size_t rbase = ((size_t)bh * NN + q0 + wid * 16) * 32;
        const uint32_t* r0h = g_qh + rbase + (size_t)lr * 32;
        const uint32_t* r1h = r0h + 8 * 32;
        const uint32_t* r0l = g_ql + rbase + (size_t)lr * 32;
        const uint32_t* r1l = r0l + 8 * 32;
#pragma unroll
        for (int c = 0; c < 4; c++) {
            qh[c][0] = r0h[8 * c + lc2];     qh[c][1] = r1h[8 * c + lc2];
            qh[c][2] = r0h[8 * c + lc2 + 4]; qh[c][3] = r1h[8 * c + lc2 + 4];
            ql[c][0] = r0l[8 * c + lc2];     ql[c][1] = r1l[8 * c + lc2];
            ql[c][2] = r0l[8 * c + lc2 + 4]; ql[c][3] = r1l[8 * c + lc2 + 4];
        }
    }

    float o[8][4] = {};
    float m0 = -1e30f, m1 = -1e30f, l0 = 0.f, l1 = 0.f;

    const uint4* gkh = (const uint4*)g_kh + ((size_t)bh * NN) * 8;
    const uint4* gkl = (const uint4*)g_kl + ((size_t)bh * NN) * 8;
    const uint4* gvh = (const uint4*)g_vh + ((size_t)bh * DD) * 256;
    const uint4* gvl = (const uint4*)g_vl + ((size_t)bh * DD) * 256;

    for (int k0 = 0; k0 < NN; k0 += 128) {
        __syncthreads();
#pragma unroll
        for (int i = 0; i < 4; i++) {
            int idx = t + i * 256;
            int key = idx >> 3, c4 = idx & 7;
            int dst = key * 8 + (c4 ^ (key & 7));
            ((uint4*)Ksh)[dst] = gkh[(size_t)(k0 + key) * 8 + c4];
            ((uint4*)Ksl)[dst] = gkl[(size_t)(k0 + key) * 8 + c4];
            int d = idx >> 4, v4 = idx & 15;
            int vdst = d * 16 + (v4 ^ (d & 7));
            ((uint4*)Vsh)[vdst] = gvh[(size_t)d * 256 + (k0 >> 3) + v4];
            ((uint4*)Vsl)[vdst] = gvl[(size_t)d * 256 + (k0 >> 3) + v4];
        }
        __syncthreads();

        float s[16][4] = {};
        const int xr = lr << 2;
#pragma unroll
        for (int c = 0; c < 4; c++) {
            const int col0i = (8 * c + lc2) ^ xr;
#pragma unroll
            for (int t16 = 0; t16 < 16; t16++) {
                const int base = (8 * t16 + lr) * 32;
                uint32_t bh2[2] = {Ksh[base + col0i], Ksh[base + (col0i ^ 4)]};
                uint32_t bl2[2] = {Ksl[base + col0i], Ksl[base + (col0i ^ 4)]};
                mma16816(s[t16], qh[c], bh2);
                mma16816(s[t16], ql[c], bh2);
                mma16816(s[t16], qh[c], bl2);
            }
        }

        float mx0 = -1e30f, mx1 = -1e30f;
#pragma unroll
        for (int t16 = 0; t16 < 16; t16++) {
            mx0 = fmaxf(mx0, fmaxf(s[t16][0], s[t16][1]));
            mx1 = fmaxf(mx1, fmaxf(s[t16][2], s[t16][3]));
        }
#pragma unroll
        for (int off = 1; off < 4; off <<= 1) {
            mx0 = fmaxf(mx0, __shfl_xor_sync(0xffffffffu, mx0, off));
            mx1 = fmaxf(mx1, __shfl_xor_sync(0xffffffffu, mx1, off));
        }
        float mn0 = fmaxf(m0, mx0), mn1 = fmaxf(m1, mx1);
        float cr0 = __expf(m0 - mn0), cr1 = __expf(m1 - mn1);
        float rs0 = 0.f, rs1 = 0.f;
#pragma unroll
        for (int t16 = 0; t16 < 16; t16++) {
            s[t16][0] = __expf(s[t16][0] - mn0);
            s[t16][1] = __expf(s[t16][1] - mn0);
            s[t16][2] = __expf(s[t16][2] - mn1);
            s[t16][3] = __expf(s[t16][3] - mn1);
            rs0 += s[t16][0] + s[t16][1];
            rs1 += s[t16][2] + s[t16][3];
        }
#pragma unroll
        for (int off = 1; off < 4; off <<= 1) {
            rs0 += __shfl_xor_sync(0xffffffffu, rs0, off);
            rs1 += __shfl_xor_sync(0xffffffffu, rs1, off);
        }
        l0 = l0 * cr0 + rs0; m0 = mn0;
        l1 = l1 * cr1 + rs1; m1 = mn1;
#pragma unroll
        for (int nf = 0; nf < 8; nf++) {
            o[nf][0] *= cr0; o[nf][1] *= cr0;
            o[nf][2] *= cr1; o[nf][3] *= cr1;
        }

#pragma unroll
        for (int c = 0; c < 8; c++) {
            uint32_t ph[4], pl[4];
#pragma unroll
            for (int u = 0; u < 2; u++) {
                const float* sv = s[2 * c + u];
                ph[2 * u]     = packbf(sv[0], sv[1]);
                ph[2 * u + 1] = packbf(sv[2], sv[3]);
                __nv_bfloat162 hp0 = *(__nv_bfloat162*)&ph[2 * u];
                __nv_bfloat162 hp1 = *(__nv_bfloat162*)&ph[2 * u + 1];
                pl[2 * u]     = packbf(sv[0] - __low2float(hp0), sv[1] - __high2float(hp0));
                pl[2 * u + 1] = packbf(sv[2] - __low2float(hp1), sv[3] - __high2float(hp1));
            }
            const int vc0 = (8 * c + lc2) ^ xr;
#pragma unroll
            for (int nf = 0; nf < 8; nf++) {
                const int base = (8 * nf + lr) * 64;
                uint32_t vh2[2] = {Vsh[base + vc0], Vsh[base + (vc0 ^ 4)]};
                uint32_t vl2[2] = {Vsl[base + vc0], Vsl[base + (vc0 ^ 4)]};
                mma16816(o[nf], ph, vh2);
                mma16816(o[nf], pl, vh2);
                mma16816(o[nf], ph, vl2);
            }
        }
    }

    // epilogue: O/l -> bf16 hi/lo in g_atth/g_attl [B,N,C]
    const int b = blockIdx.z, h = blockIdx.y;
    const float i0 = 1.0f / l0, i1 = 1.0f / l1;
    const int n0 = q0 + wid * 16 + lr;
#pragma unroll
    for (int nf = 0; nf < 8; nf++) {
        const int d = 8 * nf + 2 * lc2;
        const size_t cidx = (size_t)(h * DD + d) >> 1;
        {
            float v0 = o[nf][0] * i0, v1 = o[nf][1] * i0;
            __nv_bfloat16 h0 = __float2bfloat16(v0), h1 = __float2bfloat16(v1);
            size_t row = (size_t)(b * NN + n0) * CW + cidx;
            g_atth[row] = packbf(v0, v1);
            g_attl[row] = packbf(v0 - __bfloat162float(h0), v1 - __bfloat162float(h1));
        }
        {
            float v0 = o[nf][2] * i1, v1 = o[nf][3] * i1;
            __nv_bfloat16 h0 = __float2bfloat16(v0), h1 = __float2bfloat16(v1);
            size_t row = (size_t)(b * NN + n0 + 8) * CW + cidx;
            g_atth[row] = packbf(v0, v1);
            g_attl[row] = packbf(v0 - __bfloat162float(h0), v1 - __bfloat162float(h1));
        }
    }
}

// ---------------------------------------------------------------------------
// proj: out = att @ w_proj^T + bias (fp32 out)
// ---------------------------------------------------------------------------
__global__ __launch_bounds__(256, 2) void proj_mma(const float* __restrict__ bias,
                                                   float* __restrict__ out) {
    const int row0 = blockIdx.y * 128;
    const int col0 = blockIdx.x * 128;
    float acc[2][8][4] = {};
    bf16gemm(g_atth, g_attl, g_wph, g_wpl, row0, col0, acc);

    const int t = threadIdx.x, wid = t >> 5, lane = t & 31;
    const int wm = wid & 3, wn = wid >> 2;
    const int lr = lane >> 2, lc2 = lane & 3;
#pragma unroll
    for (int mf = 0; mf < 2; mf++) {
        const int rbase = row0 + wm * 32 + mf * 16 + lr;
#pragma unroll
        for (int half = 0; half < 2; half++) {
            const int r = rbase + half * 8;
#pragma unroll
            for (int nf = 0; nf < 8; nf++) {
                const int c = col0 + wn * 64 + nf * 8 + lc2 * 2;
                *(float2*)(out + (size_t)r * CC + c) =
                    make_float2(acc[mf][nf][half * 2] + bias[c],
                                acc[mf][nf][half * 2 + 1] + bias[c + 1]);
            }
        }
    }
}

// ---------------------------------------------------------------------------
extern "C" void kernel_launch(void* const* d_in, const int* in_sizes, int n_in,
                              void* d_out, int out_size) {
    const float* x      = (const float*)d_in[0];
    const float* w_qkv  = (const float*)d_in[1];
    const float* w_proj = (const float*)d_in[2];
    const float* b_proj = (const float*)d_in[3];
    float* out = (float*)d_out;

    cudaFuncSetAttribute(qkv_mma,  cudaFuncAttributeMaxDynamicSharedMemorySize, SMEM_GEMM);
    cudaFuncSetAttribute(proj_mma, cudaFuncAttributeMaxDynamicSharedMemorySize, SMEM_GEMM);
    cudaFuncSetAttribute(attn_mma, cudaFuncAttributeMaxDynamicSharedMemorySize, SMEM_ATTN);

    uint32_t *p_xh, *p_xl, *p_wqh, *p_wql, *p_wph, *p_wpl;
    cudaGetSymbolAddress((void**)&p_xh,  g_xh);
    cudaGetSymbolAddress((void**)&p_xl,  g_xl);
    cudaGetSymbolAddress((void**)&p_wqh, g_wqh);
    cudaGetSymbolAddress((void**)&p_wql, g_wql);
    cudaGetSymbolAddress((void**)&p_wph, g_wph);
    cudaGetSymbolAddress((void**)&p_wpl, g_wpl);

    const int n4x = MM * CC / 4, n4q = 3 * CC * CC / 4, n4p = CC * CC / 4;
    cvt_hilo<<<(n4x + 255) / 256, 256>>>(x, p_xh, p_xl, n4x);
    cvt_hilo<<<(n4q + 255) / 256, 256>>>(w_qkv, p_wqh, p_wql, n4q);
    cvt_hilo<<<(n4p + 255) / 256, 256>>>(w_proj, p_wph, p_wpl, n4p);

    dim3 g1(3 * CC / 128, MM / 128);        // 24 x 32
    qkv_mma<<<g1, 256, SMEM_GEMM>>>();

    dim3 g2(NN / 128, HH, BB);              // 16 x 16 x 2
    attn_mma<<<g2, 256, SMEM_ATTN>>>();

    dim3 g3(CC / 128, MM / 128);            // 8 x 32
    proj_mma<<<g3, 256, SMEM_GEMM>>>(b_proj, out);
}